// round 6
// baseline (speedup 1.0000x reference)
#include <cuda_runtime.h>
#include <cstdint>

// Problem constants
#define B   8
#define T   2048
#define C   256
#define L   32
#define DQ  512
#define WSZ 32
#define NCH 8
#define CIC 4
#define NW  2017      // T - WSZ + 1
#define NS  2045      // T - CIC + 1
#define DSPLIT 16     // d-split for enc partial GEMM

// ---------------- scratch (device globals; no allocs allowed) ----------------
__device__ float g_part1[DSPLIT * B * L * C];   // 4 MB
__device__ float g_part2[DSPLIT * B * L * C];   // 4 MB
__device__ float g_enc1[B * L * C];             // 256 KB
__device__ float g_enc2[B * L * C];             // 256 KB (pre-scaled by 0.25)
__device__ int   g_labels[B * T];               // 64 KB

// ---------------------------------------------------------------------------
// K1a: partial enc GEMMs.  enc{1,2}[b,l,c] = sum_d query[b,l,d]*W{1,2}[d,c]
// grid (DSPLIT, B), 256 threads.
// ---------------------------------------------------------------------------
__global__ void k_enc_partial(const float* __restrict__ query,
                              const float* __restrict__ W1,
                              const float* __restrict__ W2) {
    __shared__ float q_s[L * 32];   // [l][dd]
    const int b  = blockIdx.y;
    const int dc = blockIdx.x;
    const int d0 = dc * 32;

    for (int i = threadIdx.x; i < L * 32; i += 256) {
        int l = i >> 5, dd = i & 31;
        q_s[i] = query[((b * L + l) * DQ) + d0 + dd];
    }
    __syncthreads();

    const int warp = threadIdx.x >> 5, lane = threadIdx.x & 31;

    float4 a1[4][2], a2[4][2];
#pragma unroll
    for (int i = 0; i < 4; i++)
#pragma unroll
        for (int p = 0; p < 2; p++) {
            a1[i][p] = make_float4(0.f, 0.f, 0.f, 0.f);
            a2[i][p] = make_float4(0.f, 0.f, 0.f, 0.f);
        }

    for (int dd = 0; dd < 32; dd++) {
        const int d = d0 + dd;
        const float4* w1r = (const float4*)(W1 + d * C);
        const float4* w2r = (const float4*)(W2 + d * C);
        float4 w1a = w1r[lane], w1b = w1r[lane + 32];
        float4 w2a = w2r[lane], w2b = w2r[lane + 32];
#pragma unroll
        for (int i = 0; i < 4; i++) {
            float q = q_s[(warp * 4 + i) * 32 + dd];
            a1[i][0].x += q * w1a.x; a1[i][0].y += q * w1a.y;
            a1[i][0].z += q * w1a.z; a1[i][0].w += q * w1a.w;
            a1[i][1].x += q * w1b.x; a1[i][1].y += q * w1b.y;
            a1[i][1].z += q * w1b.z; a1[i][1].w += q * w1b.w;
            a2[i][0].x += q * w2a.x; a2[i][0].y += q * w2a.y;
            a2[i][0].z += q * w2a.z; a2[i][0].w += q * w2a.w;
            a2[i][1].x += q * w2b.x; a2[i][1].y += q * w2b.y;
            a2[i][1].z += q * w2b.z; a2[i][1].w += q * w2b.w;
        }
    }

#pragma unroll
    for (int i = 0; i < 4; i++) {
        int l = warp * 4 + i;
        float4* p1 = (float4*)(g_part1 + (((size_t)dc * B + b) * L + l) * C);
        float4* p2 = (float4*)(g_part2 + (((size_t)dc * B + b) * L + l) * C);
        p1[lane] = a1[i][0]; p1[lane + 32] = a1[i][1];
        p2[lane] = a2[i][0]; p2[lane + 32] = a2[i][1];
    }
}

// K1b: reduce d-split partials + bias. grid (B*L), 256 threads (thread = c).
// NOTE: g_enc2 is pre-scaled by 0.25 (the mean4 divisor) — exact pow2 scale.
__global__ void k_enc_reduce(const float* __restrict__ b1,
                             const float* __restrict__ b2) {
    const int b = blockIdx.x >> 5, l = blockIdx.x & 31, c = threadIdx.x;
    float s1 = 0.f, s2 = 0.f;
#pragma unroll
    for (int dc = 0; dc < DSPLIT; dc++) {
        size_t idx = (((size_t)dc * B + b) * L + l) * C + c;
        s1 += g_part1[idx];
        s2 += g_part2[idx];
    }
    g_enc1[(b * L + l) * C + c] = s1 + b1[c];
    g_enc2[(b * L + l) * C + c] = 0.25f * (s2 + b2[c]);
}

// ---------------------------------------------------------------------------
// K2: clip_labels[b,t] = argmax_l sum_c vis[b,t,c]*enc1[b,l,c]
// grid (T/32, B), 256 threads.
// ---------------------------------------------------------------------------
__global__ void k_labels(const float* __restrict__ vis) {
    __shared__ float e_s[L * C];   // 32 KB
    const int b = blockIdx.y, t0 = blockIdx.x * 32;

    for (int i = threadIdx.x; i < L * C; i += 256)
        e_s[i] = g_enc1[b * L * C + i];
    __syncthreads();

    const int warp = threadIdx.x >> 5, lane = threadIdx.x & 31;
    const int tb = t0 + warp * 4;

    float v[4][8];
#pragma unroll
    for (int i = 0; i < 4; i++) {
        const float* vr = vis + ((size_t)(b * T + tb + i)) * C;
#pragma unroll
        for (int j = 0; j < 8; j++) v[i][j] = vr[lane + 32 * j];
    }

    float best[4]; int bl[4];
#pragma unroll
    for (int i = 0; i < 4; i++) { best[i] = -3.4e38f; bl[i] = 0; }

    for (int l = 0; l < L; l++) {
        float s0 = 0.f, s1 = 0.f, s2 = 0.f, s3 = 0.f;
#pragma unroll
        for (int j = 0; j < 8; j++) {
            float e = e_s[l * C + lane + 32 * j];
            s0 += v[0][j] * e;
            s1 += v[1][j] * e;
            s2 += v[2][j] * e;
            s3 += v[3][j] * e;
        }
#pragma unroll
        for (int o = 16; o; o >>= 1) {
            s0 += __shfl_xor_sync(0xffffffffu, s0, o);
            s1 += __shfl_xor_sync(0xffffffffu, s1, o);
            s2 += __shfl_xor_sync(0xffffffffu, s2, o);
            s3 += __shfl_xor_sync(0xffffffffu, s3, o);
        }
        if (s0 > best[0]) { best[0] = s0; bl[0] = l; }
        if (s1 > best[1]) { best[1] = s1; bl[1] = l; }
        if (s2 > best[2]) { best[2] = s2; bl[2] = l; }
        if (s3 > best[3]) { best[3] = s3; bl[3] = l; }
    }
    if (lane == 0) {
#pragma unroll
        for (int i = 0; i < 4; i++) g_labels[b * T + tb + i] = bl[i];
    }
}

// ---------------------------------------------------------------------------
// K4 (register sliding window, no big smem):
// out[b,w,k,c] = g_enc2[b, maj4(w+4k), c] * sum4(vis[b, w+4k .. +3, c])
// 512 threads: warp = (half, k). Each warp owns half a row (512B) and slides
// a 4-row register ring along s = w + 4k. vis + enc2 read from global
// (L1/L2-hot; ~0 smem -> L1D ~228KB, 3 blocks/SM, 48 warps).
// grid (ceil(NW/32), B).
// ---------------------------------------------------------------------------
#define WT 32
__global__ void __launch_bounds__(512, 3)
k_out(const float* __restrict__ vis, float* __restrict__ out) {
    __shared__ int lab_s[WT + 32];
    __shared__ int maj_s[WT + 28];

    const int b  = blockIdx.y;
    const int w0 = blockIdx.x * WT;
    const int tid = threadIdx.x;

    if (tid < WT + 32) {
        int t = w0 + tid;
        lab_s[tid] = (t < T) ? g_labels[b * T + t] : 0;
    }
    __syncthreads();
    if (tid < WT + 28) {
        int la[4];
#pragma unroll
        for (int i = 0; i < 4; i++) la[i] = lab_s[tid + i];
        int bc = 0, blab = L;
#pragma unroll
        for (int i = 0; i < 4; i++) {
            int cnt = (la[0] == la[i]) + (la[1] == la[i]) +
                      (la[2] == la[i]) + (la[3] == la[i]);
            if (cnt > bc || (cnt == bc && la[i] < blab)) { bc = cnt; blab = la[i]; }
        }
        maj_s[tid] = blab;
    }
    __syncthreads();

    const int warp = tid >> 5, lane = tid & 31;
    const int k    = warp & 7;          // chunk index
    const int half = warp >> 3;         // which 512B half of the row
    const int coff = half * 32 + lane;  // float4 offset within a 256-float row

    const int s0 = w0 + 4 * k;

    // vis column pointer: row r is at vcol[r*64] (row = 64 float4s)
    const float4* vcol = (const float4*)(vis + ((size_t)b * T) * C) + coff;
    const float4* encb = (const float4*)(g_enc2 + (size_t)b * L * C) + coff;
    float4* orow = (float4*)(out + (((size_t)(b * NW + w0)) * NCH + k) * C) + coff;

    // 4-row register ring + running sum
    float4 r0 = vcol[(size_t)(s0 + 0) * 64];
    float4 r1 = vcol[(size_t)(s0 + 1) * 64];
    float4 r2 = vcol[(size_t)(s0 + 2) * 64];
    float4 r3 = vcol[(size_t)(s0 + 3) * 64];
    float4 sum = make_float4(r0.x + r1.x + r2.x + r3.x,
                             r0.y + r1.y + r2.y + r3.y,
                             r0.z + r1.z + r2.z + r3.z,
                             r0.w + r1.w + r2.w + r3.w);

    const float4* ventry = vcol + (size_t)(s0 + 4) * 64;   // entering row for wl=0
    const int* majp = maj_s + 4 * k;

#pragma unroll 4
    for (int wl = 0; wl < WT; wl++) {
        const int w = w0 + wl;
        if (w >= NW) break;

        const int lbl = majp[wl];
        float4 e = encb[(size_t)lbl * 64];   // pre-scaled by 0.25

        orow[(size_t)wl * (NCH * 64)] = make_float4(sum.x * e.x, sum.y * e.y,
                                                    sum.z * e.z, sum.w * e.w);

        if (wl < WT - 1 && w + 1 < NW) {
            float4 nv = ventry[(size_t)wl * 64];
            float4 ol;
            switch (wl & 3) {
                case 0: ol = r0; r0 = nv; break;
                case 1: ol = r1; r1 = nv; break;
                case 2: ol = r2; r2 = nv; break;
                default: ol = r3; r3 = nv; break;
            }
            sum.x += nv.x - ol.x; sum.y += nv.y - ol.y;
            sum.z += nv.z - ol.z; sum.w += nv.w - ol.w;
        }
    }
}

// ---------------------------------------------------------------------------
extern "C" void kernel_launch(void* const* d_in, const int* in_sizes, int n_in,
                              void* d_out, int out_size) {
    const float* vis   = (const float*)d_in[0];  // (B,T,C)
    const float* query = (const float*)d_in[1];  // (B,L,DQ)
    const float* W1    = (const float*)d_in[2];  // (DQ,C)
    const float* b1    = (const float*)d_in[3];  // (C,)
    const float* W2    = (const float*)d_in[4];  // (DQ,C)
    const float* b2    = (const float*)d_in[5];  // (C,)
    float* out = (float*)d_out;

    (void)in_sizes; (void)n_in; (void)out_size;

    k_enc_partial<<<dim3(DSPLIT, B), 256>>>(query, W1, W2);
    k_enc_reduce<<<B * L, 256>>>(b1, b2);
    k_labels<<<dim3(T / 32, B), 256>>>(vis);
    k_out<<<dim3((NW + WT - 1) / WT, B), 512>>>(vis, out);
}

// round 7
// speedup vs baseline: 1.1509x; 1.1509x over previous
#include <cuda_runtime.h>
#include <cstdint>

// Problem constants
#define B   8
#define T   2048
#define C   256
#define L   32
#define DQ  512
#define WSZ 32
#define NCH 8
#define CIC 4
#define NW  2017      // T - WSZ + 1
#define NS  2045      // T - CIC + 1
#define DSPLIT 16     // d-split for enc partial GEMM

// ---------------- scratch (device globals; no allocs allowed) ----------------
__device__ float g_part1[DSPLIT * B * L * C];   // 4 MB
__device__ float g_part2[DSPLIT * B * L * C];   // 4 MB
__device__ float g_enc1[B * L * C];             // 256 KB
__device__ float g_enc2[B * L * C];             // 256 KB (pre-scaled by 0.25)
__device__ int   g_labels[B * T];               // 64 KB

// ---------------------------------------------------------------------------
// K1a: partial enc GEMMs.  enc{1,2}[b,l,c] = sum_d query[b,l,d]*W{1,2}[d,c]
// grid (DSPLIT, B), 256 threads.
// ---------------------------------------------------------------------------
__global__ void k_enc_partial(const float* __restrict__ query,
                              const float* __restrict__ W1,
                              const float* __restrict__ W2) {
    __shared__ float q_s[L * 32];   // [l][dd]
    const int b  = blockIdx.y;
    const int dc = blockIdx.x;
    const int d0 = dc * 32;

    for (int i = threadIdx.x; i < L * 32; i += 256) {
        int l = i >> 5, dd = i & 31;
        q_s[i] = query[((b * L + l) * DQ) + d0 + dd];
    }
    __syncthreads();

    const int warp = threadIdx.x >> 5, lane = threadIdx.x & 31;

    float4 a1[4][2], a2[4][2];
#pragma unroll
    for (int i = 0; i < 4; i++)
#pragma unroll
        for (int p = 0; p < 2; p++) {
            a1[i][p] = make_float4(0.f, 0.f, 0.f, 0.f);
            a2[i][p] = make_float4(0.f, 0.f, 0.f, 0.f);
        }

    for (int dd = 0; dd < 32; dd++) {
        const int d = d0 + dd;
        const float4* w1r = (const float4*)(W1 + d * C);
        const float4* w2r = (const float4*)(W2 + d * C);
        float4 w1a = w1r[lane], w1b = w1r[lane + 32];
        float4 w2a = w2r[lane], w2b = w2r[lane + 32];
#pragma unroll
        for (int i = 0; i < 4; i++) {
            float q = q_s[(warp * 4 + i) * 32 + dd];
            a1[i][0].x += q * w1a.x; a1[i][0].y += q * w1a.y;
            a1[i][0].z += q * w1a.z; a1[i][0].w += q * w1a.w;
            a1[i][1].x += q * w1b.x; a1[i][1].y += q * w1b.y;
            a1[i][1].z += q * w1b.z; a1[i][1].w += q * w1b.w;
            a2[i][0].x += q * w2a.x; a2[i][0].y += q * w2a.y;
            a2[i][0].z += q * w2a.z; a2[i][0].w += q * w2a.w;
            a2[i][1].x += q * w2b.x; a2[i][1].y += q * w2b.y;
            a2[i][1].z += q * w2b.z; a2[i][1].w += q * w2b.w;
        }
    }

#pragma unroll
    for (int i = 0; i < 4; i++) {
        int l = warp * 4 + i;
        float4* p1 = (float4*)(g_part1 + (((size_t)dc * B + b) * L + l) * C);
        float4* p2 = (float4*)(g_part2 + (((size_t)dc * B + b) * L + l) * C);
        p1[lane] = a1[i][0]; p1[lane + 32] = a1[i][1];
        p2[lane] = a2[i][0]; p2[lane + 32] = a2[i][1];
    }
}

// K1b: reduce d-split partials + bias. grid (B*L), 256 threads (thread = c).
// NOTE: g_enc2 is pre-scaled by 0.25 (the mean4 divisor) — exact pow2 scale.
__global__ void k_enc_reduce(const float* __restrict__ b1,
                             const float* __restrict__ b2) {
    const int b = blockIdx.x >> 5, l = blockIdx.x & 31, c = threadIdx.x;
    float s1 = 0.f, s2 = 0.f;
#pragma unroll
    for (int dc = 0; dc < DSPLIT; dc++) {
        size_t idx = (((size_t)dc * B + b) * L + l) * C + c;
        s1 += g_part1[idx];
        s2 += g_part2[idx];
    }
    g_enc1[(b * L + l) * C + c] = s1 + b1[c];
    g_enc2[(b * L + l) * C + c] = 0.25f * (s2 + b2[c]);
}

// ---------------------------------------------------------------------------
// K2: clip_labels[b,t] = argmax_l sum_c vis[b,t,c]*enc1[b,l,c]
// grid (T/32, B), 256 threads.
// ---------------------------------------------------------------------------
__global__ void k_labels(const float* __restrict__ vis) {
    __shared__ float e_s[L * C];   // 32 KB
    const int b = blockIdx.y, t0 = blockIdx.x * 32;

    for (int i = threadIdx.x; i < L * C; i += 256)
        e_s[i] = g_enc1[b * L * C + i];
    __syncthreads();

    const int warp = threadIdx.x >> 5, lane = threadIdx.x & 31;
    const int tb = t0 + warp * 4;

    float v[4][8];
#pragma unroll
    for (int i = 0; i < 4; i++) {
        const float* vr = vis + ((size_t)(b * T + tb + i)) * C;
#pragma unroll
        for (int j = 0; j < 8; j++) v[i][j] = vr[lane + 32 * j];
    }

    float best[4]; int bl[4];
#pragma unroll
    for (int i = 0; i < 4; i++) { best[i] = -3.4e38f; bl[i] = 0; }

    for (int l = 0; l < L; l++) {
        float s0 = 0.f, s1 = 0.f, s2 = 0.f, s3 = 0.f;
#pragma unroll
        for (int j = 0; j < 8; j++) {
            float e = e_s[l * C + lane + 32 * j];
            s0 += v[0][j] * e;
            s1 += v[1][j] * e;
            s2 += v[2][j] * e;
            s3 += v[3][j] * e;
        }
#pragma unroll
        for (int o = 16; o; o >>= 1) {
            s0 += __shfl_xor_sync(0xffffffffu, s0, o);
            s1 += __shfl_xor_sync(0xffffffffu, s1, o);
            s2 += __shfl_xor_sync(0xffffffffu, s2, o);
            s3 += __shfl_xor_sync(0xffffffffu, s3, o);
        }
        if (s0 > best[0]) { best[0] = s0; bl[0] = l; }
        if (s1 > best[1]) { best[1] = s1; bl[1] = l; }
        if (s2 > best[2]) { best[2] = s2; bl[2] = l; }
        if (s3 > best[3]) { best[3] = s3; bl[3] = l; }
    }
    if (lane == 0) {
#pragma unroll
        for (int i = 0; i < 4; i++) g_labels[b * T + tb + i] = bl[i];
    }
}

// ---------------------------------------------------------------------------
// K4 (s-major, 8x store reuse):
// val(b,s,c) = enc2[b, maj4(s), c] * sum4(vis[b, s..s+3, c])   (enc2 holds /4)
// out[b, s-4k, k, :] = val(b,s,:)  for all valid k in [0,7].
// One compute per distinct s, EIGHT coalesced stores. Block = 256 thr =
// 4 s-chunks x 2 row-halves; each warp slides a 4-row register ring over
// 8 consecutive s. grid (ceil(NS/32), B).
// ---------------------------------------------------------------------------
#define SBLK 32   // s per block
#define SCH  8    // s per warp chunk
__global__ void __launch_bounds__(256)
k_out(const float* __restrict__ vis, float* __restrict__ out) {
    __shared__ int lab_s[SBLK + 8];
    __shared__ int maj_s[SBLK];

    const int b   = blockIdx.y;
    const int s0b = blockIdx.x * SBLK;
    const int tid = threadIdx.x;

    if (tid < SBLK + 8) {
        int t = s0b + tid;
        lab_s[tid] = (t < T) ? g_labels[b * T + t] : 0;
    }
    __syncthreads();
    if (tid < SBLK) {
        int la[4];
#pragma unroll
        for (int i = 0; i < 4; i++) la[i] = lab_s[tid + i];
        int bc = 0, blab = L;
#pragma unroll
        for (int i = 0; i < 4; i++) {
            int cnt = (la[0] == la[i]) + (la[1] == la[i]) +
                      (la[2] == la[i]) + (la[3] == la[i]);
            if (cnt > bc || (cnt == bc && la[i] < blab)) { bc = cnt; blab = la[i]; }
        }
        maj_s[tid] = blab;
    }
    __syncthreads();

    const int warp = tid >> 5, lane = tid & 31;
    const int half = warp & 1;            // which 512B half of the 1KB row
    const int j    = warp >> 1;           // s-chunk 0..3
    const int coff = half * 32 + lane;    // float4 index within a row
    const int sw0  = s0b + j * SCH;

    const float4* vcol = (const float4*)(vis + ((size_t)b * T) * C) + coff;
    const float4* encb = (const float4*)(g_enc2 + (size_t)b * L * C) + coff;
    float4* outb = (float4*)out + (size_t)b * NW * (NCH * 64) + coff;

    // 4-row register ring + running sum for s = sw0
    float4 r0 = vcol[(size_t)(sw0 + 0) * 64];
    float4 r1 = vcol[(size_t)(sw0 + 1) * 64];
    float4 r2 = vcol[(size_t)(sw0 + 2) * 64];
    float4 r3 = vcol[(size_t)(sw0 + 3) * 64];
    float4 sum = make_float4(r0.x + r1.x + r2.x + r3.x,
                             r0.y + r1.y + r2.y + r3.y,
                             r0.z + r1.z + r2.z + r3.z,
                             r0.w + r1.w + r2.w + r3.w);

#pragma unroll
    for (int wl = 0; wl < SCH; wl++) {
        const int s = sw0 + wl;
        if (s >= NS) break;

        const int lbl = maj_s[j * SCH + wl];
        float4 e = encb[(size_t)lbl * 64];          // pre-scaled by 0.25
        float4 val = make_float4(sum.x * e.x, sum.y * e.y,
                                 sum.z * e.z, sum.w * e.w);

        // valid k: w = s-4k in [0, NW)
        const int kmax = (s >> 2) < 7 ? (s >> 2) : 7;
        const int kmin = (s <= NW - 1) ? 0 : ((s - (NW - 1) + 3) >> 2);

        float4* p = outb + ((size_t)(8 * s - 31 * kmin)) * 64;
        for (int k = kmin; k <= kmax; k++) {
            *p = val;
            p -= 31 * 64;
        }

        // slide window: + row (s+4), - row s
        if (wl < SCH - 1 && s + 1 < NS) {
            float4 nv = vcol[(size_t)(s + 4) * 64];
            float4 ol;
            if ((wl & 3) == 0)      { ol = r0; r0 = nv; }
            else if ((wl & 3) == 1) { ol = r1; r1 = nv; }
            else if ((wl & 3) == 2) { ol = r2; r2 = nv; }
            else                    { ol = r3; r3 = nv; }
            sum.x += nv.x - ol.x; sum.y += nv.y - ol.y;
            sum.z += nv.z - ol.z; sum.w += nv.w - ol.w;
        }
    }
}

// ---------------------------------------------------------------------------
extern "C" void kernel_launch(void* const* d_in, const int* in_sizes, int n_in,
                              void* d_out, int out_size) {
    const float* vis   = (const float*)d_in[0];  // (B,T,C)
    const float* query = (const float*)d_in[1];  // (B,L,DQ)
    const float* W1    = (const float*)d_in[2];  // (DQ,C)
    const float* b1    = (const float*)d_in[3];  // (C,)
    const float* W2    = (const float*)d_in[4];  // (DQ,C)
    const float* b2    = (const float*)d_in[5];  // (C,)
    float* out = (float*)d_out;

    (void)in_sizes; (void)n_in; (void)out_size;

    k_enc_partial<<<dim3(DSPLIT, B), 256>>>(query, W1, W2);
    k_enc_reduce<<<B * L, 256>>>(b1, b2);
    k_labels<<<dim3(T / 32, B), 256>>>(vis);
    k_out<<<dim3((NS + SBLK - 1) / SBLK, B), 256>>>(vis, out);
}

// round 9
// speedup vs baseline: 1.2953x; 1.1254x over previous
#include <cuda_runtime.h>
#include <cstdint>

// Problem constants
#define B   8
#define T   2048
#define C   256
#define L   32
#define DQ  512
#define WSZ 32
#define NCH 8
#define CIC 4
#define NW  2017      // T - WSZ + 1
#define NS  2045      // T - CIC + 1
#define DSPLIT 16     // d-split for enc partial GEMM

// ---------------- scratch (device globals; no allocs allowed) ----------------
__device__ float g_part1[DSPLIT * B * L * C];   // 4 MB
__device__ float g_part2[DSPLIT * B * L * C];   // 4 MB
__device__ float g_enc1[B * L * C];             // 256 KB
__device__ float g_enc2[B * L * C];             // 256 KB (pre-scaled by 0.25)
__device__ int   g_labels[B * T];               // 64 KB

// ---------------------------------------------------------------------------
// K1a: partial enc GEMMs.  enc{1,2}[b,l,c] = sum_d query[b,l,d]*W{1,2}[d,c]
// grid (DSPLIT, B), 256 threads.
// ---------------------------------------------------------------------------
__global__ void k_enc_partial(const float* __restrict__ query,
                              const float* __restrict__ W1,
                              const float* __restrict__ W2) {
    __shared__ float q_s[L * 32];   // [l][dd]
    const int b  = blockIdx.y;
    const int dc = blockIdx.x;
    const int d0 = dc * 32;

    for (int i = threadIdx.x; i < L * 32; i += 256) {
        int l = i >> 5, dd = i & 31;
        q_s[i] = query[((b * L + l) * DQ) + d0 + dd];
    }
    __syncthreads();

    const int warp = threadIdx.x >> 5, lane = threadIdx.x & 31;

    float4 a1[4][2], a2[4][2];
#pragma unroll
    for (int i = 0; i < 4; i++)
#pragma unroll
        for (int p = 0; p < 2; p++) {
            a1[i][p] = make_float4(0.f, 0.f, 0.f, 0.f);
            a2[i][p] = make_float4(0.f, 0.f, 0.f, 0.f);
        }

    for (int dd = 0; dd < 32; dd++) {
        const int d = d0 + dd;
        const float4* w1r = (const float4*)(W1 + d * C);
        const float4* w2r = (const float4*)(W2 + d * C);
        float4 w1a = w1r[lane], w1b = w1r[lane + 32];
        float4 w2a = w2r[lane], w2b = w2r[lane + 32];
#pragma unroll
        for (int i = 0; i < 4; i++) {
            float q = q_s[(warp * 4 + i) * 32 + dd];
            a1[i][0].x += q * w1a.x; a1[i][0].y += q * w1a.y;
            a1[i][0].z += q * w1a.z; a1[i][0].w += q * w1a.w;
            a1[i][1].x += q * w1b.x; a1[i][1].y += q * w1b.y;
            a1[i][1].z += q * w1b.z; a1[i][1].w += q * w1b.w;
            a2[i][0].x += q * w2a.x; a2[i][0].y += q * w2a.y;
            a2[i][0].z += q * w2a.z; a2[i][0].w += q * w2a.w;
            a2[i][1].x += q * w2b.x; a2[i][1].y += q * w2b.y;
            a2[i][1].z += q * w2b.z; a2[i][1].w += q * w2b.w;
        }
    }

#pragma unroll
    for (int i = 0; i < 4; i++) {
        int l = warp * 4 + i;
        float4* p1 = (float4*)(g_part1 + (((size_t)dc * B + b) * L + l) * C);
        float4* p2 = (float4*)(g_part2 + (((size_t)dc * B + b) * L + l) * C);
        p1[lane] = a1[i][0]; p1[lane + 32] = a1[i][1];
        p2[lane] = a2[i][0]; p2[lane + 32] = a2[i][1];
    }
}

// K1b: reduce d-split partials + bias. grid (B*L), 256 threads (thread = c).
// NOTE: g_enc2 is pre-scaled by 0.25 (the mean4 divisor) — exact pow2 scale.
__global__ void k_enc_reduce(const float* __restrict__ b1,
                             const float* __restrict__ b2) {
    const int b = blockIdx.x >> 5, l = blockIdx.x & 31, c = threadIdx.x;
    float s1 = 0.f, s2 = 0.f;
#pragma unroll
    for (int dc = 0; dc < DSPLIT; dc++) {
        size_t idx = (((size_t)dc * B + b) * L + l) * C + c;
        s1 += g_part1[idx];
        s2 += g_part2[idx];
    }
    g_enc1[(b * L + l) * C + c] = s1 + b1[c];
    g_enc2[(b * L + l) * C + c] = 0.25f * (s2 + b2[c]);
}

// ---------------------------------------------------------------------------
// K2: clip_labels[b,t] = argmax_l sum_c vis[b,t,c]*enc1[b,l,c]
// grid (T/32, B), 256 threads. float4 loads; lane owns c = 4*lane(+128).
// Reduction order per lane identical to scalar version (same c grouping).
// ---------------------------------------------------------------------------
__global__ void k_labels(const float* __restrict__ vis) {
    __shared__ float e_s[L * C];   // 32 KB
    const int b = blockIdx.y, t0 = blockIdx.x * 32;

    for (int i = threadIdx.x; i < L * C; i += 256)
        e_s[i] = g_enc1[b * L * C + i];
    __syncthreads();

    const int warp = threadIdx.x >> 5, lane = threadIdx.x & 31;
    const int tb = t0 + warp * 4;

    float4 v[4][2];
#pragma unroll
    for (int i = 0; i < 4; i++) {
        const float4* vr = (const float4*)(vis + ((size_t)(b * T + tb + i)) * C);
        v[i][0] = vr[lane];
        v[i][1] = vr[lane + 32];
    }

    float best[4]; int bl[4];
#pragma unroll
    for (int i = 0; i < 4; i++) { best[i] = -3.4e38f; bl[i] = 0; }

    for (int l = 0; l < L; l++) {
        const float4* er = (const float4*)(e_s + l * C);
        float4 e0 = er[lane], e1 = er[lane + 32];
        float s0, s1, s2, s3;
        {
            s0 = v[0][0].x * e0.x + v[0][0].y * e0.y + v[0][0].z * e0.z + v[0][0].w * e0.w
               + v[0][1].x * e1.x + v[0][1].y * e1.y + v[0][1].z * e1.z + v[0][1].w * e1.w;
            s1 = v[1][0].x * e0.x + v[1][0].y * e0.y + v[1][0].z * e0.z + v[1][0].w * e0.w
               + v[1][1].x * e1.x + v[1][1].y * e1.y + v[1][1].z * e1.z + v[1][1].w * e1.w;
            s2 = v[2][0].x * e0.x + v[2][0].y * e0.y + v[2][0].z * e0.z + v[2][0].w * e0.w
               + v[2][1].x * e1.x + v[2][1].y * e1.y + v[2][1].z * e1.z + v[2][1].w * e1.w;
            s3 = v[3][0].x * e0.x + v[3][0].y * e0.y + v[3][0].z * e0.z + v[3][0].w * e0.w
               + v[3][1].x * e1.x + v[3][1].y * e1.y + v[3][1].z * e1.z + v[3][1].w * e1.w;
        }
#pragma unroll
        for (int o = 16; o; o >>= 1) {
            s0 += __shfl_xor_sync(0xffffffffu, s0, o);
            s1 += __shfl_xor_sync(0xffffffffu, s1, o);
            s2 += __shfl_xor_sync(0xffffffffu, s2, o);
            s3 += __shfl_xor_sync(0xffffffffu, s3, o);
        }
        if (s0 > best[0]) { best[0] = s0; bl[0] = l; }
        if (s1 > best[1]) { best[1] = s1; bl[1] = l; }
        if (s2 > best[2]) { best[2] = s2; bl[2] = l; }
        if (s3 > best[3]) { best[3] = s3; bl[3] = l; }
    }
    if (lane == 0) {
#pragma unroll
        for (int i = 0; i < 4; i++) g_labels[b * T + tb + i] = bl[i];
    }
}

// ---------------------------------------------------------------------------
// K4 (s-major, 8x store reuse, high-occupancy):
// val(b,s,c) = enc2[b, maj4(s), c] * sum4(vis[b, s..s+3, c])   (enc2 holds /4)
// out[b, s-4k, k, :] = val(b,s,:)  for all valid k in [0,7]. Streaming stores.
// Block = 256 thr = 4 s-chunks x 2 row-halves; warp slides a 4-row register
// ring over 4 consecutive s. grid (ceil(NS/16), B) = 1024 blocks -> 8192 warps.
// ---------------------------------------------------------------------------
#define SBLK 16   // s per block
#define SCH  4    // s per warp chunk
__global__ void __launch_bounds__(256)
k_out(const float* __restrict__ vis, float* __restrict__ out) {
    __shared__ int lab_s[SBLK + 8];
    __shared__ int maj_s[SBLK];

    const int b   = blockIdx.y;
    const int s0b = blockIdx.x * SBLK;
    const int tid = threadIdx.x;

    if (tid < SBLK + 8) {
        int t = s0b + tid;
        lab_s[tid] = (t < T) ? g_labels[b * T + t] : 0;
    }
    __syncthreads();
    if (tid < SBLK) {
        int la[4];
#pragma unroll
        for (int i = 0; i < 4; i++) la[i] = lab_s[tid + i];
        int bc = 0, blab = L;
#pragma unroll
        for (int i = 0; i < 4; i++) {
            int cnt = (la[0] == la[i]) + (la[1] == la[i]) +
                      (la[2] == la[i]) + (la[3] == la[i]);
            if (cnt > bc || (cnt == bc && la[i] < blab)) { bc = cnt; blab = la[i]; }
        }
        maj_s[tid] = blab;
    }
    __syncthreads();

    const int warp = tid >> 5, lane = tid & 31;
    const int half = warp & 1;            // which 512B half of the 1KB row
    const int j    = warp >> 1;           // s-chunk 0..3
    const int coff = half * 32 + lane;    // float4 index within a row
    const int sw0  = s0b + j * SCH;

    const float4* vcol = (const float4*)(vis + ((size_t)b * T) * C) + coff;
    const float4* encb = (const float4*)(g_enc2 + (size_t)b * L * C) + coff;
    float4* outb = (float4*)out + (size_t)b * NW * (NCH * 64) + coff;

    // 4-row register ring + running sum for s = sw0
    float4 r0 = vcol[(size_t)(sw0 + 0) * 64];
    float4 r1 = vcol[(size_t)(sw0 + 1) * 64];
    float4 r2 = vcol[(size_t)(sw0 + 2) * 64];
    float4 r3 = vcol[(size_t)(sw0 + 3) * 64];
    float4 sum = make_float4(r0.x + r1.x + r2.x + r3.x,
                             r0.y + r1.y + r2.y + r3.y,
                             r0.z + r1.z + r2.z + r3.z,
                             r0.w + r1.w + r2.w + r3.w);

#pragma unroll
    for (int wl = 0; wl < SCH; wl++) {
        const int s = sw0 + wl;
        if (s >= NS) break;

        const int lbl = maj_s[j * SCH + wl];
        float4 e = encb[(size_t)lbl * 64];          // pre-scaled by 0.25
        float4 val = make_float4(sum.x * e.x, sum.y * e.y,
                                 sum.z * e.z, sum.w * e.w);

        // valid k: w = s-4k in [0, NW)
        const int kmax = (s >> 2) < 7 ? (s >> 2) : 7;
        const int kmin = (s <= NW - 1) ? 0 : ((s - (NW - 1) + 3) >> 2);

        float4* p = outb + ((size_t)(8 * s - 31 * kmin)) * 64;
        for (int k = kmin; k <= kmax; k++) {
            __stcs(p, val);                         // streaming: never re-read
            p -= 31 * 64;
        }

        // slide window: + row (s+4), - row s
        if (wl < SCH - 1 && s + 1 < NS) {
            float4 nv = vcol[(size_t)(s + 4) * 64];
            float4 ol;
            if (wl == 0)      { ol = r0; r0 = nv; }
            else if (wl == 1) { ol = r1; r1 = nv; }
            else              { ol = r2; r2 = nv; }
            sum.x += nv.x - ol.x; sum.y += nv.y - ol.y;
            sum.z += nv.z - ol.z; sum.w += nv.w - ol.w;
        }
    }
}

// ---------------------------------------------------------------------------
extern "C" void kernel_launch(void* const* d_in, const int* in_sizes, int n_in,
                              void* d_out, int out_size) {
    const float* vis   = (const float*)d_in[0];  // (B,T,C)
    const float* query = (const float*)d_in[1];  // (B,L,DQ)
    const float* W1    = (const float*)d_in[2];  // (DQ,C)
    const float* b1    = (const float*)d_in[3];  // (C,)
    const float* W2    = (const float*)d_in[4];  // (DQ,C)
    const float* b2    = (const float*)d_in[5];  // (C,)
    float* out = (float*)d_out;

    (void)in_sizes; (void)n_in; (void)out_size;

    k_enc_partial<<<dim3(DSPLIT, B), 256>>>(query, W1, W2);
    k_enc_reduce<<<B * L, 256>>>(b1, b2);
    k_labels<<<dim3(T / 32, B), 256>>>(vis);
    k_out<<<dim3((NS + SBLK - 1) / SBLK, B), 256>>>(vis, out);
}

// round 10
// speedup vs baseline: 1.4679x; 1.1333x over previous
#include <cuda_runtime.h>
#include <cstdint>

// Problem constants
#define B   8
#define T   2048
#define C   256
#define L   32
#define DQ  512
#define WSZ 32
#define NCH 8
#define CIC 4
#define NW  2017      // T - WSZ + 1
#define NS  2045      // T - CIC + 1
#define DSPLIT 16     // d-split for enc partial GEMM

// ---------------- scratch (device globals; no allocs allowed) ----------------
__device__ float g_part1[DSPLIT * B * L * C];   // 4 MB
__device__ float g_part2[DSPLIT * B * L * C];   // 4 MB
__device__ float g_enc1[B * L * C];             // 256 KB
__device__ float g_enc2[B * L * C];             // 256 KB (pre-scaled by 0.25)
__device__ int   g_labels[B * T];               // 64 KB

// ---------------------------------------------------------------------------
// K1a: partial enc GEMMs.  enc{1,2}[b,l,c] = sum_d query[b,l,d]*W{1,2}[d,c]
// grid (DSPLIT, B), 256 threads.
// ---------------------------------------------------------------------------
__global__ void k_enc_partial(const float* __restrict__ query,
                              const float* __restrict__ W1,
                              const float* __restrict__ W2) {
    __shared__ float q_s[L * 32];   // [l][dd]
    const int b  = blockIdx.y;
    const int dc = blockIdx.x;
    const int d0 = dc * 32;

    for (int i = threadIdx.x; i < L * 32; i += 256) {
        int l = i >> 5, dd = i & 31;
        q_s[i] = query[((b * L + l) * DQ) + d0 + dd];
    }
    __syncthreads();

    const int warp = threadIdx.x >> 5, lane = threadIdx.x & 31;

    float4 a1[4][2], a2[4][2];
#pragma unroll
    for (int i = 0; i < 4; i++)
#pragma unroll
        for (int p = 0; p < 2; p++) {
            a1[i][p] = make_float4(0.f, 0.f, 0.f, 0.f);
            a2[i][p] = make_float4(0.f, 0.f, 0.f, 0.f);
        }

    for (int dd = 0; dd < 32; dd++) {
        const int d = d0 + dd;
        const float4* w1r = (const float4*)(W1 + d * C);
        const float4* w2r = (const float4*)(W2 + d * C);
        float4 w1a = w1r[lane], w1b = w1r[lane + 32];
        float4 w2a = w2r[lane], w2b = w2r[lane + 32];
#pragma unroll
        for (int i = 0; i < 4; i++) {
            float q = q_s[(warp * 4 + i) * 32 + dd];
            a1[i][0].x += q * w1a.x; a1[i][0].y += q * w1a.y;
            a1[i][0].z += q * w1a.z; a1[i][0].w += q * w1a.w;
            a1[i][1].x += q * w1b.x; a1[i][1].y += q * w1b.y;
            a1[i][1].z += q * w1b.z; a1[i][1].w += q * w1b.w;
            a2[i][0].x += q * w2a.x; a2[i][0].y += q * w2a.y;
            a2[i][0].z += q * w2a.z; a2[i][0].w += q * w2a.w;
            a2[i][1].x += q * w2b.x; a2[i][1].y += q * w2b.y;
            a2[i][1].z += q * w2b.z; a2[i][1].w += q * w2b.w;
        }
    }

#pragma unroll
    for (int i = 0; i < 4; i++) {
        int l = warp * 4 + i;
        float4* p1 = (float4*)(g_part1 + (((size_t)dc * B + b) * L + l) * C);
        float4* p2 = (float4*)(g_part2 + (((size_t)dc * B + b) * L + l) * C);
        p1[lane] = a1[i][0]; p1[lane + 32] = a1[i][1];
        p2[lane] = a2[i][0]; p2[lane + 32] = a2[i][1];
    }
}

// K1b: reduce d-split partials + bias. grid (B*L), 256 threads (thread = c).
// NOTE: g_enc2 is pre-scaled by 0.25 (the mean4 divisor) — exact pow2 scale.
__global__ void k_enc_reduce(const float* __restrict__ b1,
                             const float* __restrict__ b2) {
    const int b = blockIdx.x >> 5, l = blockIdx.x & 31, c = threadIdx.x;
    float s1 = 0.f, s2 = 0.f;
#pragma unroll
    for (int dc = 0; dc < DSPLIT; dc++) {
        size_t idx = (((size_t)dc * B + b) * L + l) * C + c;
        s1 += g_part1[idx];
        s2 += g_part2[idx];
    }
    g_enc1[(b * L + l) * C + c] = s1 + b1[c];
    g_enc2[(b * L + l) * C + c] = 0.25f * (s2 + b2[c]);
}

// ---------------------------------------------------------------------------
// K2 (GEMM-tiled, shuffle-free): sim[t,l] = sum_c vis[b,t,c]*enc1[b,l,c],
// labels[b,t] = argmax_l (first max).
// Block = 128 thr computes a 64t x 32l tile; thread = 4t x 4l accumulators
// (ILP 16). enc1 staged TRANSPOSED [c][l] (stride 36, conflict-free LDS.128
// over l); vis staged [t][c] stride 65 (conflict-free scalar broadcast).
// grid (T/64, B).
// ---------------------------------------------------------------------------
#define VP 65
#define EP 36
__global__ void __launch_bounds__(128)
k_labels(const float* __restrict__ vis) {
    __shared__ float vis_s[64 * VP];    // 16.6 KB
    __shared__ float enc_s[64 * EP];    //  9.2 KB
    __shared__ float sim_s[64 * 33];    //  8.4 KB

    const int b  = blockIdx.y;
    const int t0 = blockIdx.x * 64;
    const int tid = threadIdx.x;
    const int ti = tid >> 3;          // 0..15 -> t rows ti*4..+3
    const int li = (tid & 7) * 4;     // 0,4,...,28

    float acc[4][4];
#pragma unroll
    for (int i = 0; i < 4; i++)
#pragma unroll
        for (int j = 0; j < 4; j++) acc[i][j] = 0.f;

    for (int ch = 0; ch < 4; ch++) {
        // stage vis rows t0..t0+63, cols ch*64..+63  (1024 float4 slots)
#pragma unroll
        for (int k = 0; k < 8; k++) {
            int slot = tid + k * 128;
            int r = slot >> 4, c4 = slot & 15;
            float4 vv = *((const float4*)(vis + ((size_t)(b * T + t0 + r)) * C + ch * 64) + c4);
            float* dst = vis_s + r * VP + c4 * 4;
            dst[0] = vv.x; dst[1] = vv.y; dst[2] = vv.z; dst[3] = vv.w;
        }
        // stage enc1 transposed: enc_s[c][l]  (512 float4 slots over (l, c4))
#pragma unroll
        for (int k = 0; k < 4; k++) {
            int slot = tid + k * 128;
            int l = slot >> 4, c4 = slot & 15;
            float4 ev = *((const float4*)(g_enc1 + (size_t)(b * L + l) * C + ch * 64) + c4);
            enc_s[(c4 * 4 + 0) * EP + l] = ev.x;
            enc_s[(c4 * 4 + 1) * EP + l] = ev.y;
            enc_s[(c4 * 4 + 2) * EP + l] = ev.z;
            enc_s[(c4 * 4 + 3) * EP + l] = ev.w;
        }
        __syncthreads();

#pragma unroll 4
        for (int c = 0; c < 64; c++) {
            float va0 = vis_s[(ti * 4 + 0) * VP + c];
            float va1 = vis_s[(ti * 4 + 1) * VP + c];
            float va2 = vis_s[(ti * 4 + 2) * VP + c];
            float va3 = vis_s[(ti * 4 + 3) * VP + c];
            float4 ea = *(const float4*)(enc_s + c * EP + li);
            acc[0][0] += va0 * ea.x; acc[0][1] += va0 * ea.y;
            acc[0][2] += va0 * ea.z; acc[0][3] += va0 * ea.w;
            acc[1][0] += va1 * ea.x; acc[1][1] += va1 * ea.y;
            acc[1][2] += va1 * ea.z; acc[1][3] += va1 * ea.w;
            acc[2][0] += va2 * ea.x; acc[2][1] += va2 * ea.y;
            acc[2][2] += va2 * ea.z; acc[2][3] += va2 * ea.w;
            acc[3][0] += va3 * ea.x; acc[3][1] += va3 * ea.y;
            acc[3][2] += va3 * ea.z; acc[3][3] += va3 * ea.w;
        }
        __syncthreads();
    }

    // epilogue: dump sim tile, per-t argmax (first max, ascending l)
#pragma unroll
    for (int i = 0; i < 4; i++)
#pragma unroll
        for (int j = 0; j < 4; j++)
            sim_s[(ti * 4 + i) * 33 + li + j] = acc[i][j];
    __syncthreads();

    if (tid < 64) {
        const float* row = sim_s + tid * 33;
        float best = row[0]; int bl = 0;
#pragma unroll
        for (int l = 1; l < L; l++) {
            float v = row[l];
            if (v > best) { best = v; bl = l; }
        }
        g_labels[b * T + t0 + tid] = bl;
    }
}

// ---------------------------------------------------------------------------
// K4 (s-major, 8x store reuse, prefetched, max-occupancy):
// val(b,s,c) = enc2[b, maj4(s), c] * sum4(vis[b, s..s+3, c])   (enc2 holds /4)
// out[b, s-4k, k, :] = val  for all valid k. Streaming stores.
// Block = 256 thr = 4 s-chunks(2 s each) x 2 row-halves. All 7 LDG.128
// (5 vis rows + 2 enc2 rows) issued up-front -> MLP 7, then 16 independent
// STG.128. grid (ceil(NS/8), B) = 2048 blocks -> 16K warps.
// ---------------------------------------------------------------------------
#define SBLK 8
__global__ void __launch_bounds__(256)
k_out(const float* __restrict__ vis, float* __restrict__ out) {
    __shared__ int lab_s[SBLK + 4];
    __shared__ int maj_s[SBLK];

    const int b   = blockIdx.y;
    const int s0b = blockIdx.x * SBLK;
    const int tid = threadIdx.x;

    if (tid < SBLK + 4) {
        int t = s0b + tid;
        lab_s[tid] = (t < T) ? g_labels[b * T + t] : 0;
    }
    __syncthreads();
    if (tid < SBLK) {
        int la[4];
#pragma unroll
        for (int i = 0; i < 4; i++) la[i] = lab_s[tid + i];
        int bc = 0, blab = L;
#pragma unroll
        for (int i = 0; i < 4; i++) {
            int cnt = (la[0] == la[i]) + (la[1] == la[i]) +
                      (la[2] == la[i]) + (la[3] == la[i]);
            if (cnt > bc || (cnt == bc && la[i] < blab)) { bc = cnt; blab = la[i]; }
        }
        maj_s[tid] = blab;
    }
    __syncthreads();

    const int warp = tid >> 5, lane = tid & 31;
    const int half = warp & 1;            // which 512B half of the 1KB row
    const int j    = warp >> 1;           // s-pair 0..3
    const int coff = half * 32 + lane;    // float4 index within a row
    const int s    = s0b + j * 2;

    const bool v0 = (s < NS);
    const bool v1 = (s + 1 < NS);
    if (!v0) return;

    const float4* vcol = (const float4*)(vis + ((size_t)b * T) * C) + coff;
    const float4* encb = (const float4*)(g_enc2 + (size_t)b * L * C) + coff;
    float4* outb = (float4*)out + (size_t)b * NW * (NCH * 64) + coff;

    const int l0 = maj_s[j * 2];
    const int l1 = maj_s[j * 2 + 1];

    // issue all global loads up-front (MLP 7)
    float4 r0 = vcol[(size_t)(s + 0) * 64];
    float4 r1 = vcol[(size_t)(s + 1) * 64];
    float4 r2 = vcol[(size_t)(s + 2) * 64];
    float4 r3 = vcol[(size_t)(s + 3) * 64];
    float4 r4 = v1 ? vcol[(size_t)(s + 4) * 64] : make_float4(0.f, 0.f, 0.f, 0.f);
    float4 e0 = encb[(size_t)l0 * 64];
    float4 e1 = v1 ? encb[(size_t)l1 * 64] : make_float4(0.f, 0.f, 0.f, 0.f);

    // window s
    {
        float4 val = make_float4((r0.x + r1.x + r2.x + r3.x) * e0.x,
                                 (r0.y + r1.y + r2.y + r3.y) * e0.y,
                                 (r0.z + r1.z + r2.z + r3.z) * e0.z,
                                 (r0.w + r1.w + r2.w + r3.w) * e0.w);
        const int kmax = (s >> 2) < 7 ? (s >> 2) : 7;
        const int kmin = (s <= NW - 1) ? 0 : ((s - (NW - 1) + 3) >> 2);
        float4* p = outb + ((size_t)(8 * s - 31 * kmin)) * 64;
        for (int k = kmin; k <= kmax; k++) {
            __stcs(p, val);
            p -= 31 * 64;
        }
    }
    // window s+1
    if (v1) {
        const int s1 = s + 1;
        float4 val = make_float4((r1.x + r2.x + r3.x + r4.x) * e1.x,
                                 (r1.y + r2.y + r3.y + r4.y) * e1.y,
                                 (r1.z + r2.z + r3.z + r4.z) * e1.z,
                                 (r1.w + r2.w + r3.w + r4.w) * e1.w);
        const int kmax = (s1 >> 2) < 7 ? (s1 >> 2) : 7;
        const int kmin = (s1 <= NW - 1) ? 0 : ((s1 - (NW - 1) + 3) >> 2);
        float4* p = outb + ((size_t)(8 * s1 - 31 * kmin)) * 64;
        for (int k = kmin; k <= kmax; k++) {
            __stcs(p, val);
            p -= 31 * 64;
        }
    }
}

// ---------------------------------------------------------------------------
extern "C" void kernel_launch(void* const* d_in, const int* in_sizes, int n_in,
                              void* d_out, int out_size) {
    const float* vis   = (const float*)d_in[0];  // (B,T,C)
    const float* query = (const float*)d_in[1];  // (B,L,DQ)
    const float* W1    = (const float*)d_in[2];  // (DQ,C)
    const float* b1    = (const float*)d_in[3];  // (C,)
    const float* W2    = (const float*)d_in[4];  // (DQ,C)
    const float* b2    = (const float*)d_in[5];  // (C,)
    float* out = (float*)d_out;

    (void)in_sizes; (void)n_in; (void)out_size;

    k_enc_partial<<<dim3(DSPLIT, B), 256>>>(query, W1, W2);
    k_enc_reduce<<<B * L, 256>>>(b1, b2);
    k_labels<<<dim3(T / 64, B), 128>>>(vis);
    k_out<<<dim3((NS + SBLK - 1) / SBLK, B), 256>>>(vis, out);
}